// round 1
// baseline (speedup 1.0000x reference)
#include <cuda_runtime.h>
#include <math.h>

#define NN 50000
#define EE 800000
#define TT 3
#define HEADS 4
#define HDIM 32
#define IND 128   // IN_DIM = HEADS*HDIM

// ---------------- scratch (static device memory; no runtime allocs) ----------------
__device__ float g_h[(size_t)TT * NN * IND];       // 76.8 MB  projected features
__device__ float g_esrc[(size_t)TT * NN * HEADS];  // per-node src coefficients
__device__ float g_edst[(size_t)TT * NN * HEADS];  // per-node dst coefficients
__device__ float g_denom[(size_t)TT * NN * HEADS]; // softmax denominators

// ---------------- zero init (out gat-half + denom) ----------------
__global__ void zero_kernel(float* __restrict__ out) {
    int i = blockIdx.x * blockDim.x + threadIdx.x;
    const int n4 = TT * NN * (IND / 4);           // 4.8M float4 for gat half
    if (i < n4) {
        float4 z = make_float4(0.f, 0.f, 0.f, 0.f);
        reinterpret_cast<float4*>(out)[i] = z;
    }
    if (i < TT * NN * HEADS) g_denom[i] = 0.f;
}

// ---------------- GEMM: h[t] = x @ W[t]   (x:[N,128], W:[128,128]) ----------------
// block = 256 threads, computes 64 rows x 128 cols; k tiled by 32.
// thread micro-tile: 8 rows x 4 cols.
__global__ void gemm_kernel(const float* __restrict__ x, const float* __restrict__ W) {
    __shared__ float Wsh[32][IND];    // 16 KB
    __shared__ float xsh[64][32];     // 8 KB
    const int t    = blockIdx.y;
    const int row0 = blockIdx.x * 64;
    const int tc   = threadIdx.x & 31;   // col group (lane)
    const int tr   = threadIdx.x >> 5;   // row group (warp id), 8 warps

    float4 acc[8];
#pragma unroll
    for (int i = 0; i < 8; ++i) acc[i] = make_float4(0.f, 0.f, 0.f, 0.f);

    const float* Wt = W + (size_t)t * IND * IND;

    for (int kt = 0; kt < 4; ++kt) {
        // load W tile [32 x 128]
        for (int i = threadIdx.x; i < 32 * IND; i += 256) {
            int k = i >> 7, c = i & 127;
            Wsh[k][c] = Wt[(size_t)(kt * 32 + k) * IND + c];
        }
        // load x tile [64 x 32]
        for (int i = threadIdx.x; i < 64 * 32; i += 256) {
            int r = i >> 5, kk = i & 31;
            int row = row0 + r;
            xsh[r][kk] = (row < NN) ? x[(size_t)row * IND + kt * 32 + kk] : 0.f;
        }
        __syncthreads();
#pragma unroll
        for (int kk = 0; kk < 32; ++kk) {
            float4 wv = *reinterpret_cast<const float4*>(&Wsh[kk][tc * 4]);
#pragma unroll
            for (int i = 0; i < 8; ++i) {
                float xv = xsh[tr * 8 + i][kk];
                acc[i].x += xv * wv.x;
                acc[i].y += xv * wv.y;
                acc[i].z += xv * wv.z;
                acc[i].w += xv * wv.w;
            }
        }
        __syncthreads();
    }
#pragma unroll
    for (int i = 0; i < 8; ++i) {
        int row = row0 + tr * 8 + i;
        if (row < NN) {
            *reinterpret_cast<float4*>(&g_h[((size_t)t * NN + row) * IND + tc * 4]) = acc[i];
        }
    }
}

// ---------------- per-node attention coefficients ----------------
__global__ void coef_kernel(const float* __restrict__ a_src, const float* __restrict__ a_dst) {
    int idx = blockIdx.x * blockDim.x + threadIdx.x;   // over T*N
    if (idx >= TT * NN) return;
    int t = idx / NN;
    const float4* hr = reinterpret_cast<const float4*>(g_h + (size_t)idx * IND);
    const float4* as = reinterpret_cast<const float4*>(a_src + (size_t)t * HEADS * HDIM);
    const float4* ad = reinterpret_cast<const float4*>(a_dst + (size_t)t * HEADS * HDIM);
    float es[HEADS] = {0.f, 0.f, 0.f, 0.f};
    float ed[HEADS] = {0.f, 0.f, 0.f, 0.f};
#pragma unroll
    for (int c4 = 0; c4 < IND / 4; ++c4) {
        float4 hv = hr[c4];
        float4 av = __ldg(&as[c4]);
        float4 dv = __ldg(&ad[c4]);
        int h = c4 >> 3;  // 8 float4 per head
        es[h] += hv.x * av.x + hv.y * av.y + hv.z * av.z + hv.w * av.w;
        ed[h] += hv.x * dv.x + hv.y * dv.y + hv.z * dv.z + hv.w * dv.w;
    }
#pragma unroll
    for (int h = 0; h < HEADS; ++h) {
        g_esrc[(size_t)idx * HEADS + h] = es[h];
        g_edst[(size_t)idx * HEADS + h] = ed[h];
    }
}

// ---------------- edge pass: softmax-weighted scatter (one warp per edge) ----------------
// exp(e) without max-subtraction: mathematically identical softmax; |e| is O(1) here.
__global__ void edge_kernel(const int* __restrict__ edges, float* __restrict__ out, int t) {
    int gwarp = (blockIdx.x * blockDim.x + threadIdx.x) >> 5;
    int lane  = threadIdx.x & 31;
    if (gwarp >= EE) return;
    const int* eb = edges + (size_t)t * 2 * EE;
    int src = __ldg(eb + gwarp);
    int dst = __ldg(eb + EE + gwarp);

    float p = 0.f;
    if (lane < HEADS) {
        float v = g_esrc[((size_t)t * NN + src) * HEADS + lane]
                + g_edst[((size_t)t * NN + dst) * HEADS + lane];
        v = (v > 0.f) ? v : 0.2f * v;          // leaky_relu
        p = expf(v);
        atomicAdd(&g_denom[((size_t)t * NN + dst) * HEADS + lane], p);
    }
    p = __shfl_sync(0xffffffffu, p, lane >> 3);  // head = lane/8 (4 floats per lane)

    float4 hv = __ldg(reinterpret_cast<const float4*>(
        g_h + ((size_t)t * NN + src) * IND) + lane);
    float mx = hv.x * p, my = hv.y * p, mz = hv.z * p, mw = hv.w * p;
    float* dptr = out + ((size_t)t * NN + dst) * IND + lane * 4;
    asm volatile("red.global.add.v4.f32 [%0], {%1,%2,%3,%4};"
                 :: "l"(dptr), "f"(mx), "f"(my), "f"(mz), "f"(mw) : "memory");
}

// ---------------- finalize: elu(agg/denom), duplicate to gcn half ----------------
__global__ void finalize_kernel(float* __restrict__ out) {
    int i = blockIdx.x * blockDim.x + threadIdx.x;      // over T*N*32 float4
    const int total4 = TT * NN * (IND / 4);
    if (i >= total4) return;
    size_t tn = (size_t)i >> 5;                          // t*N+n
    int c4   = i & 31;
    int head = c4 >> 3;
    float4 v = reinterpret_cast<float4*>(out)[i];
    float inv = 1.f / (g_denom[tn * HEADS + head] + 1e-9f);
    v.x *= inv; v.y *= inv; v.z *= inv; v.w *= inv;
    v.x = (v.x > 0.f) ? v.x : expm1f(v.x);
    v.y = (v.y > 0.f) ? v.y : expm1f(v.y);
    v.z = (v.z > 0.f) ? v.z : expm1f(v.z);
    v.w = (v.w > 0.f) ? v.w : expm1f(v.w);
    reinterpret_cast<float4*>(out)[i] = v;                                   // gat
    reinterpret_cast<float4*>(out)[(size_t)total4 + i] = v;                  // gcn (identical)
}

// ---------------- launch ----------------
extern "C" void kernel_launch(void* const* d_in, const int* in_sizes, int n_in,
                              void* d_out, int out_size) {
    const float* embedding = (const float*)d_in[0];   // [N,128]
    const int*   edges     = (const int*)d_in[1];     // [3,2,E]
    const float* W         = (const float*)d_in[2];   // [3,128,4,32]
    const float* a_src     = (const float*)d_in[3];   // [3,4,32]
    const float* a_dst     = (const float*)d_in[4];   // [3,4,32]
    float* out = (float*)d_out;                       // [2,3,N,128]

    (void)in_sizes; (void)n_in; (void)out_size;

    // 1) zero gat half of out + denoms
    {
        int n = TT * NN * (IND / 4);
        zero_kernel<<<(n + 255) / 256, 256>>>(out);
    }
    // 2) GEMMs: h[t] = x @ W[t]
    {
        dim3 grid((NN + 63) / 64, TT);
        gemm_kernel<<<grid, 256>>>(embedding, W);
    }
    // 3) attention coefficients
    {
        int n = TT * NN;
        coef_kernel<<<(n + 255) / 256, 256>>>(a_src, a_dst);
    }
    // 4) edge aggregation, one kernel per type (L2 residency of h_t + agg_t)
    {
        int threads = 256;
        int blocks = (EE * 32 + threads - 1) / threads;   // warp per edge
        for (int t = 0; t < TT; ++t)
            edge_kernel<<<blocks, threads>>>(edges, out, t);
    }
    // 5) finalize + duplicate
    {
        int n = TT * NN * (IND / 4);
        finalize_kernel<<<(n + 255) / 256, 256>>>(out);
    }
}

// round 2
// speedup vs baseline: 1.6758x; 1.6758x over previous
#include <cuda_runtime.h>
#include <math.h>

#define NN 50000
#define EE 800000
#define TT 3
#define HEADS 4
#define HDIM 32
#define IND 128            // IN_DIM = HEADS*HDIM
#define TN (TT * NN)       // 150000
#define SCAN_CH 1024
#define SCAN_NB ((TN + SCAN_CH - 1) / SCAN_CH)   // 147

// ---------------- static device scratch ----------------
__device__ float g_h[(size_t)TT * NN * IND];        // 76.8 MB projected features
__device__ float g_esrc[(size_t)TN * HEADS];        // per-node src coefficients
__device__ float g_edst[(size_t)TN * HEADS];        // per-node dst coefficients
__device__ int   g_cnt[TN];                         // in-degree histogram
__device__ int   g_off[TN + 1];                     // CSR offsets (exclusive scan)
__device__ int   g_cur[TN];                         // scatter cursors
__device__ int   g_srcbuf[(size_t)TT * EE];         // src id per dst-sorted slot
__device__ int   g_bsum[SCAN_NB];                   // scan block sums

// ---------------- zero histogram ----------------
__global__ void zero_cnt_kernel() {
    int i = blockIdx.x * blockDim.x + threadIdx.x;
    if (i < TN) g_cnt[i] = 0;
}

// ---------------- GEMM h[t] = x @ W[t], fused coef epilogue ----------------
// block = 256, tile 64 rows x 128 cols, k-tile 32; micro-tile 8x4 per thread.
__global__ void gemm_kernel(const float* __restrict__ x, const float* __restrict__ W,
                            const float* __restrict__ a_src, const float* __restrict__ a_dst) {
    __shared__ float Wsh[32][IND];    // 16 KB
    __shared__ float xsh[64][32];     // 8 KB
    const int t    = blockIdx.y;
    const int row0 = blockIdx.x * 64;
    const int tc   = threadIdx.x & 31;   // lane: col group
    const int tr   = threadIdx.x >> 5;   // warp: row group

    float4 acc[8];
#pragma unroll
    for (int i = 0; i < 8; ++i) acc[i] = make_float4(0.f, 0.f, 0.f, 0.f);

    const float* Wt = W + (size_t)t * IND * IND;

    for (int kt = 0; kt < 4; ++kt) {
        for (int i = threadIdx.x; i < 32 * IND; i += 256) {
            int k = i >> 7, c = i & 127;
            Wsh[k][c] = Wt[(size_t)(kt * 32 + k) * IND + c];
        }
        for (int i = threadIdx.x; i < 64 * 32; i += 256) {
            int r = i >> 5, kk = i & 31;
            int row = row0 + r;
            xsh[r][kk] = (row < NN) ? x[(size_t)row * IND + kt * 32 + kk] : 0.f;
        }
        __syncthreads();
#pragma unroll
        for (int kk = 0; kk < 32; ++kk) {
            float4 wv = *reinterpret_cast<const float4*>(&Wsh[kk][tc * 4]);
#pragma unroll
            for (int i = 0; i < 8; ++i) {
                float xv = xsh[tr * 8 + i][kk];
                acc[i].x += xv * wv.x;
                acc[i].y += xv * wv.y;
                acc[i].z += xv * wv.z;
                acc[i].w += xv * wv.w;
            }
        }
        __syncthreads();
    }

    // a-vectors for this thread's 4 columns
    float4 av = __ldg(reinterpret_cast<const float4*>(a_src + (size_t)t * IND + tc * 4));
    float4 dv = __ldg(reinterpret_cast<const float4*>(a_dst + (size_t)t * IND + tc * 4));
    const int head = tc >> 3;

#pragma unroll
    for (int i = 0; i < 8; ++i) {
        int row = row0 + tr * 8 + i;
        if (row < NN) {
            *reinterpret_cast<float4*>(&g_h[((size_t)t * NN + row) * IND + tc * 4]) = acc[i];
            // fused coefficient epilogue: reduce over the 8 lanes of this head
            float s = acc[i].x * av.x + acc[i].y * av.y + acc[i].z * av.z + acc[i].w * av.w;
            float d = acc[i].x * dv.x + acc[i].y * dv.y + acc[i].z * dv.z + acc[i].w * dv.w;
            s += __shfl_xor_sync(0xffffffffu, s, 1);
            d += __shfl_xor_sync(0xffffffffu, d, 1);
            s += __shfl_xor_sync(0xffffffffu, s, 2);
            d += __shfl_xor_sync(0xffffffffu, d, 2);
            s += __shfl_xor_sync(0xffffffffu, s, 4);
            d += __shfl_xor_sync(0xffffffffu, d, 4);
            if ((tc & 7) == 0) {
                g_esrc[((size_t)t * NN + row) * HEADS + head] = s;
                g_edst[((size_t)t * NN + row) * HEADS + head] = d;
            }
        }
    }
}

// ---------------- histogram of dst in-degree ----------------
__global__ void hist_kernel(const int* __restrict__ edges) {
    int e = blockIdx.x * blockDim.x + threadIdx.x;
    int t = blockIdx.y;
    if (e >= EE) return;
    int dst = __ldg(edges + (size_t)t * 2 * EE + EE + e);
    atomicAdd(&g_cnt[t * NN + dst], 1);
}

// ---------------- hierarchical exclusive scan ----------------
__device__ __forceinline__ int warp_incl_scan(int x) {
#pragma unroll
    for (int o = 1; o < 32; o <<= 1) {
        int y = __shfl_up_sync(0xffffffffu, x, o);
        if ((threadIdx.x & 31) >= o) x += y;
    }
    return x;
}

__global__ void scan1_kernel() {
    __shared__ int wsum[32];
    int i = blockIdx.x * SCAN_CH + threadIdx.x;
    int v = (i < TN) ? g_cnt[i] : 0;
    int x = warp_incl_scan(v);                       // inclusive within warp
    int wid = threadIdx.x >> 5;
    if ((threadIdx.x & 31) == 31) wsum[wid] = x;
    __syncthreads();
    if (threadIdx.x < 32) {
        int s = wsum[threadIdx.x];
        int xs = warp_incl_scan(s);
        wsum[threadIdx.x] = xs - s;                  // exclusive warp offsets
    }
    __syncthreads();
    int excl = x - v + wsum[wid];
    if (i < TN) g_off[i] = excl;
    if (threadIdx.x == SCAN_CH - 1) g_bsum[blockIdx.x] = excl + v;  // block total
}

__global__ void scan2_kernel() {
    __shared__ int wsum[8];
    int tid = threadIdx.x;                            // 256 threads
    int v = (tid < SCAN_NB) ? g_bsum[tid] : 0;
    int x = warp_incl_scan(v);
    int wid = tid >> 5;
    if ((tid & 31) == 31) wsum[wid] = x;
    __syncthreads();
    if (tid < 8) {
        int s = wsum[tid];
        // serial exclusive scan of 8 values via shfl
        int xs = s;
#pragma unroll
        for (int o = 1; o < 8; o <<= 1) {
            int y = __shfl_up_sync(0x000000ffu, xs, o);
            if (tid >= o) xs += y;
        }
        wsum[tid] = xs - s;
    }
    __syncthreads();
    if (tid < SCAN_NB) g_bsum[tid] = x - v + wsum[wid];
}

__global__ void scan3_kernel() {
    int i = blockIdx.x * blockDim.x + threadIdx.x;
    if (i < TN) {
        int o = g_off[i] + g_bsum[i >> 10];
        g_off[i] = o;
        g_cur[i] = o;
    }
    if (i == 0) g_off[TN] = TT * EE;
}

// ---------------- scatter src ids into dst-sorted order ----------------
__global__ void scatter_kernel(const int* __restrict__ edges) {
    int e = blockIdx.x * blockDim.x + threadIdx.x;
    int t = blockIdx.y;
    if (e >= EE) return;
    const int* eb = edges + (size_t)t * 2 * EE;
    int src = __ldg(eb + e);
    int dst = __ldg(eb + EE + e);
    int pos = atomicAdd(&g_cur[t * NN + dst], 1);
    g_srcbuf[pos] = src;
}

// ---------------- gather: softmax-weighted aggregation + ELU, per dst node ----------------
__global__ void gather_kernel(float* __restrict__ out) {
    int i = (blockIdx.x * blockDim.x + threadIdx.x) >> 5;   // node id in [0, TN)
    int lane = threadIdx.x & 31;
    if (i >= TN) return;
    const int head = lane >> 3;
    const size_t tbase = (size_t)(i / NN) * NN;             // type base node index

    int beg = __ldg(&g_off[i]);
    int end = __ldg(&g_off[i + 1]);

    float edh = __ldg(&g_edst[(size_t)i * HEADS + head]);
    const float4* h4 = reinterpret_cast<const float4*>(g_h);

    float4 acc = make_float4(0.f, 0.f, 0.f, 0.f);
    float dsum = 0.f;

    int src = (beg < end) ? __ldg(&g_srcbuf[beg]) : 0;
    for (int j = beg; j < end; ++j) {
        int nsrc = (j + 1 < end) ? __ldg(&g_srcbuf[j + 1]) : 0;
        float ev = __ldg(&g_esrc[(tbase + src) * HEADS + head]);
        float4 hv = __ldg(h4 + (tbase + src) * (IND / 4) + lane);
        float v = ev + edh;
        v = (v > 0.f) ? v : 0.2f * v;         // leaky_relu
        float p = expf(v);                    // shift-free softmax (|v| is O(1))
        dsum += p;
        acc.x += hv.x * p;
        acc.y += hv.y * p;
        acc.z += hv.z * p;
        acc.w += hv.w * p;
        src = nsrc;
    }

    float inv = 1.f / (dsum + 1e-9f);
    acc.x *= inv; acc.y *= inv; acc.z *= inv; acc.w *= inv;
    acc.x = (acc.x > 0.f) ? acc.x : expm1f(acc.x);
    acc.y = (acc.y > 0.f) ? acc.y : expm1f(acc.y);
    acc.z = (acc.z > 0.f) ? acc.z : expm1f(acc.z);
    acc.w = (acc.w > 0.f) ? acc.w : expm1f(acc.w);

    const size_t total4 = (size_t)TN * (IND / 4);
    float4* o4 = reinterpret_cast<float4*>(out);
    o4[(size_t)i * (IND / 4) + lane] = acc;             // gat
    o4[total4 + (size_t)i * (IND / 4) + lane] = acc;    // gcn (identical branch)
}

// ---------------- launch ----------------
extern "C" void kernel_launch(void* const* d_in, const int* in_sizes, int n_in,
                              void* d_out, int out_size) {
    const float* embedding = (const float*)d_in[0];   // [N,128]
    const int*   edges     = (const int*)d_in[1];     // [3,2,E]
    const float* W         = (const float*)d_in[2];   // [3,128,4,32]
    const float* a_src     = (const float*)d_in[3];   // [3,4,32]
    const float* a_dst     = (const float*)d_in[4];   // [3,4,32]
    float* out = (float*)d_out;                       // [2,3,N,128]
    (void)in_sizes; (void)n_in; (void)out_size;

    zero_cnt_kernel<<<(TN + 255) / 256, 256>>>();

    {
        dim3 grid((NN + 63) / 64, TT);
        gemm_kernel<<<grid, 256>>>(embedding, W, a_src, a_dst);
    }

    {
        dim3 grid((EE + 255) / 256, TT);
        hist_kernel<<<grid, 256>>>(edges);
    }

    scan1_kernel<<<SCAN_NB, SCAN_CH>>>();
    scan2_kernel<<<1, 256>>>();
    scan3_kernel<<<(TN + 255) / 256, 256>>>();

    {
        dim3 grid((EE + 255) / 256, TT);
        scatter_kernel<<<grid, 256>>>(edges);
    }

    {
        int warps = TN;
        int blocks = (warps * 32 + 255) / 256;
        gather_kernel<<<blocks, 256>>>(out);
    }
}

// round 3
// speedup vs baseline: 1.7857x; 1.0656x over previous
#include <cuda_runtime.h>
#include <cuda_fp16.h>
#include <mma.h>
#include <math.h>

using namespace nvcuda;

#define NN 50000
#define EE 800000
#define TT 3
#define HEADS 4
#define HDIM 32
#define IND 128            // IN_DIM = HEADS*HDIM
#define TN (TT * NN)       // 150000
#define SCAN_CH 1024
#define SCAN_NB ((TN + SCAN_CH - 1) / SCAN_CH)   // 147

// ---------------- static device scratch ----------------
__device__ __half g_h[(size_t)TT * NN * IND];      // 38.4 MB projected features (fp16)
__device__ float g_esrc[(size_t)TN * HEADS];       // per-node src coefficients
__device__ float g_edst[(size_t)TN * HEADS];       // per-node dst coefficients
__device__ int   g_cnt[TN];                        // in-degree histogram
__device__ int   g_off[TN + 1];                    // CSR offsets
__device__ int   g_cur[TN];                        // scatter cursors
__device__ int   g_srcbuf[(size_t)TT * EE];        // src id per dst-sorted slot
__device__ int   g_bsum[SCAN_NB];                  // scan block sums

// ---------------- zero histogram ----------------
__global__ void zero_cnt_kernel() {
    int i = blockIdx.x * blockDim.x + threadIdx.x;
    if (i < TN) g_cnt[i] = 0;
}

// ---------------- GEMM h[t] = x @ W[t] via tf32 wmma, fused coef epilogue ----------------
// block = 256 (8 warps), tile 64 rows x 128 cols.
// warp w: rows [ (w>>1)*16, +16 ), cols [ (w&1)*64, +64 ) as 4 16x16 frags.
#define XLD 136
__global__ void gemm_kernel(const float* __restrict__ x, const float* __restrict__ W,
                            const float* __restrict__ a_src, const float* __restrict__ a_dst) {
    __shared__ float pool[64 * XLD + 16 * IND];   // 43 KB: xsh | Wsh ; Csh aliases xsh
    float* xsh = pool;                 // [64][XLD]
    float* Wsh = pool + 64 * XLD;      // [16][128]

    const int t    = blockIdx.y;
    const int row0 = blockIdx.x * 64;
    const int tid  = threadIdx.x;
    const int w    = tid >> 5;
    const int wr   = w >> 1;           // 0..3
    const int wc   = w & 1;            // 0..1
    const float* Wt = W + (size_t)t * IND * IND;

    // load x tile [64 x 128] (float4, 8 per thread)
    for (int i = tid; i < 64 * (IND / 4); i += 256) {
        int r = i >> 5, c4 = i & 31;
        int row = row0 + r;
        float4 v = (row < NN)
            ? __ldg(reinterpret_cast<const float4*>(x + (size_t)row * IND) + c4)
            : make_float4(0.f, 0.f, 0.f, 0.f);
        *reinterpret_cast<float4*>(&xsh[r * XLD + c4 * 4]) = v;
    }

    wmma::fragment<wmma::accumulator, 16, 16, 8, float> c[4];
#pragma unroll
    for (int j = 0; j < 4; ++j) wmma::fill_fragment(c[j], 0.f);

    for (int kt = 0; kt < 8; ++kt) {       // k chunks of 16
        // load W chunk [16 x 128]
        for (int i = tid; i < 16 * (IND / 4); i += 256) {
            int k = i >> 5, c4 = i & 31;
            float4 v = __ldg(reinterpret_cast<const float4*>(
                Wt + (size_t)(kt * 16 + k) * IND) + c4);
            *reinterpret_cast<float4*>(&Wsh[k * IND + c4 * 4]) = v;
        }
        __syncthreads();
#pragma unroll
        for (int k8 = 0; k8 < 2; ++k8) {
            wmma::fragment<wmma::matrix_a, 16, 16, 8, wmma::precision::tf32, wmma::row_major> a;
            wmma::load_matrix_sync(a, &xsh[(wr * 16) * XLD + kt * 16 + k8 * 8], XLD);
#pragma unroll
            for (int e = 0; e < a.num_elements; ++e) a.x[e] = wmma::__float_to_tf32(a.x[e]);
#pragma unroll
            for (int j = 0; j < 4; ++j) {
                wmma::fragment<wmma::matrix_b, 16, 16, 8, wmma::precision::tf32, wmma::row_major> b;
                wmma::load_matrix_sync(b, &Wsh[(k8 * 8) * IND + wc * 64 + j * 16], IND);
#pragma unroll
                for (int e = 0; e < b.num_elements; ++e) b.x[e] = wmma::__float_to_tf32(b.x[e]);
                wmma::mma_sync(c[j], a, b, c[j]);
            }
        }
        __syncthreads();
    }

    // dump C into smem (aliases xsh region; all mma reads done)
    float* Csh = pool;                 // [64][128]
#pragma unroll
    for (int j = 0; j < 4; ++j)
        wmma::store_matrix_sync(&Csh[(wr * 16) * IND + wc * 64 + j * 16], c[j], IND,
                                wmma::mem_row_major);
    __syncthreads();

    // epilogue: write h (fp16) + per-(row,head) coefficients
    const int tc = tid & 31;           // lane: 4 cols each
    const int tr = tid >> 5;           // warp: 8 rows each
    float4 av = __ldg(reinterpret_cast<const float4*>(a_src + (size_t)t * IND + tc * 4));
    float4 dv = __ldg(reinterpret_cast<const float4*>(a_dst + (size_t)t * IND + tc * 4));
    const int head = tc >> 3;

#pragma unroll
    for (int i = 0; i < 8; ++i) {
        int r = tr * 8 + i;
        int row = row0 + r;
        float4 hv = *reinterpret_cast<float4*>(&Csh[r * IND + tc * 4]);
        if (row < NN) {
            __half2 p0 = __floats2half2_rn(hv.x, hv.y);
            __half2 p1 = __floats2half2_rn(hv.z, hv.w);
            __half2* hp = reinterpret_cast<__half2*>(g_h + ((size_t)t * NN + row) * IND + tc * 4);
            hp[0] = p0; hp[1] = p1;
        }
        float s = hv.x * av.x + hv.y * av.y + hv.z * av.z + hv.w * av.w;
        float d = hv.x * dv.x + hv.y * dv.y + hv.z * dv.z + hv.w * dv.w;
        s += __shfl_xor_sync(0xffffffffu, s, 1);
        d += __shfl_xor_sync(0xffffffffu, d, 1);
        s += __shfl_xor_sync(0xffffffffu, s, 2);
        d += __shfl_xor_sync(0xffffffffu, d, 2);
        s += __shfl_xor_sync(0xffffffffu, s, 4);
        d += __shfl_xor_sync(0xffffffffu, d, 4);
        if ((tc & 7) == 0 && row < NN) {
            g_esrc[((size_t)t * NN + row) * HEADS + head] = s;
            g_edst[((size_t)t * NN + row) * HEADS + head] = d;
        }
    }
}

// ---------------- histogram of dst in-degree ----------------
__global__ void hist_kernel(const int* __restrict__ edges) {
    int e = blockIdx.x * blockDim.x + threadIdx.x;
    int t = blockIdx.y;
    if (e >= EE) return;
    int dst = __ldg(edges + (size_t)t * 2 * EE + EE + e);
    atomicAdd(&g_cnt[t * NN + dst], 1);
}

// ---------------- hierarchical exclusive scan ----------------
__device__ __forceinline__ int warp_incl_scan(int x) {
#pragma unroll
    for (int o = 1; o < 32; o <<= 1) {
        int y = __shfl_up_sync(0xffffffffu, x, o);
        if ((threadIdx.x & 31) >= o) x += y;
    }
    return x;
}

__global__ void scan1_kernel() {
    __shared__ int wsum[32];
    int i = blockIdx.x * SCAN_CH + threadIdx.x;
    int v = (i < TN) ? g_cnt[i] : 0;
    int x = warp_incl_scan(v);
    int wid = threadIdx.x >> 5;
    if ((threadIdx.x & 31) == 31) wsum[wid] = x;
    __syncthreads();
    if (threadIdx.x < 32) {
        int s = wsum[threadIdx.x];
        int xs = warp_incl_scan(s);
        wsum[threadIdx.x] = xs - s;
    }
    __syncthreads();
    int excl = x - v + wsum[wid];
    if (i < TN) g_off[i] = excl;
    if (threadIdx.x == SCAN_CH - 1) g_bsum[blockIdx.x] = excl + v;
}

__global__ void scan2_kernel() {
    __shared__ int wsum[8];
    int tid = threadIdx.x;
    int v = (tid < SCAN_NB) ? g_bsum[tid] : 0;
    int x = warp_incl_scan(v);
    int wid = tid >> 5;
    if ((tid & 31) == 31) wsum[wid] = x;
    __syncthreads();
    if (tid < 8) {
        int s = wsum[tid];
        int xs = s;
#pragma unroll
        for (int o = 1; o < 8; o <<= 1) {
            int y = __shfl_up_sync(0x000000ffu, xs, o);
            if (tid >= o) xs += y;
        }
        wsum[tid] = xs - s;
    }
    __syncthreads();
    if (tid < SCAN_NB) g_bsum[tid] = x - v + wsum[wid];
}

__global__ void scan3_kernel() {
    int i = blockIdx.x * blockDim.x + threadIdx.x;
    if (i < TN) {
        int o = g_off[i] + g_bsum[i >> 10];
        g_off[i] = o;
        g_cur[i] = o;
    }
    if (i == 0) g_off[TN] = TT * EE;
}

// ---------------- scatter src ids into dst-sorted order ----------------
__global__ void scatter_kernel(const int* __restrict__ edges) {
    int e = blockIdx.x * blockDim.x + threadIdx.x;
    int t = blockIdx.y;
    if (e >= EE) return;
    const int* eb = edges + (size_t)t * 2 * EE;
    int src = __ldg(eb + e);
    int dst = __ldg(eb + EE + e);
    int pos = atomicAdd(&g_cur[t * NN + dst], 1);
    g_srcbuf[pos] = src;
}

// ---------------- gather: softmax-weighted aggregation + ELU ----------------
__global__ void gather_kernel(float* __restrict__ out) {
    int i = (blockIdx.x * blockDim.x + threadIdx.x) >> 5;   // node in [0, TN)
    int lane = threadIdx.x & 31;
    if (i >= TN) return;
    const int head = lane >> 3;
    const size_t tbase = (size_t)(i / NN) * NN;

    int beg = __ldg(&g_off[i]);
    int end = __ldg(&g_off[i + 1]);

    float edh = __ldg(&g_edst[(size_t)i * HEADS + head]);
    const uint2* h2 = reinterpret_cast<const uint2*>(g_h);   // 4 halfs per uint2

    float4 acc = make_float4(0.f, 0.f, 0.f, 0.f);
    float dsum = 0.f;

    int src = (beg < end) ? __ldg(&g_srcbuf[beg]) : 0;
    for (int j = beg; j < end; ++j) {
        int nsrc = (j + 1 < end) ? __ldg(&g_srcbuf[j + 1]) : 0;
        float ev = __ldg(&g_esrc[(tbase + src) * HEADS + head]);
        uint2 hr = __ldg(h2 + (tbase + src) * (IND / 4) + lane);
        float v = ev + edh;
        v = (v > 0.f) ? v : 0.2f * v;         // leaky_relu
        float p = expf(v);                    // shift-free softmax
        dsum += p;
        __half2 h01 = *reinterpret_cast<__half2*>(&hr.x);
        __half2 h23 = *reinterpret_cast<__half2*>(&hr.y);
        float2 f01 = __half22float2(h01);
        float2 f23 = __half22float2(h23);
        acc.x += f01.x * p;
        acc.y += f01.y * p;
        acc.z += f23.x * p;
        acc.w += f23.y * p;
        src = nsrc;
    }

    float inv = 1.f / (dsum + 1e-9f);
    acc.x *= inv; acc.y *= inv; acc.z *= inv; acc.w *= inv;
    acc.x = (acc.x > 0.f) ? acc.x : expm1f(acc.x);
    acc.y = (acc.y > 0.f) ? acc.y : expm1f(acc.y);
    acc.z = (acc.z > 0.f) ? acc.z : expm1f(acc.z);
    acc.w = (acc.w > 0.f) ? acc.w : expm1f(acc.w);

    const size_t total4 = (size_t)TN * (IND / 4);
    float4* o4 = reinterpret_cast<float4*>(out);
    o4[(size_t)i * (IND / 4) + lane] = acc;             // gat
    o4[total4 + (size_t)i * (IND / 4) + lane] = acc;    // gcn (identical branch)
}

// ---------------- launch ----------------
extern "C" void kernel_launch(void* const* d_in, const int* in_sizes, int n_in,
                              void* d_out, int out_size) {
    const float* embedding = (const float*)d_in[0];   // [N,128]
    const int*   edges     = (const int*)d_in[1];     // [3,2,E]
    const float* W         = (const float*)d_in[2];   // [3,128,4,32]
    const float* a_src     = (const float*)d_in[3];   // [3,4,32]
    const float* a_dst     = (const float*)d_in[4];   // [3,4,32]
    float* out = (float*)d_out;                       // [2,3,N,128]
    (void)in_sizes; (void)n_in; (void)out_size;

    zero_cnt_kernel<<<(TN + 255) / 256, 256>>>();

    {
        dim3 grid((NN + 63) / 64, TT);
        gemm_kernel<<<grid, 256>>>(embedding, W, a_src, a_dst);
    }

    {
        dim3 grid((EE + 255) / 256, TT);
        hist_kernel<<<grid, 256>>>(edges);
    }

    scan1_kernel<<<SCAN_NB, SCAN_CH>>>();
    scan2_kernel<<<1, 256>>>();
    scan3_kernel<<<(TN + 255) / 256, 256>>>();

    {
        dim3 grid((EE + 255) / 256, TT);
        scatter_kernel<<<grid, 256>>>(edges);
    }

    {
        int blocks = (TN * 32 + 255) / 256;
        gather_kernel<<<blocks, 256>>>(out);
    }
}